// round 17
// baseline (speedup 1.0000x reference)
#include <cuda_runtime.h>
#include <cuda_bf16.h>
#include <cstdint>

// Problem constants (fixed by the dataset): B=4096 rows, C=8192 classes, K=8 positives.
#define NB 4096
#define NC 8192
#define NK 8
#define THREADS 128
#define ROWS_PER_CTA 4
#define NBLK (NB / ROWS_PER_CTA)      // 1024 CTAs
#define STAGES 4
#define CHUNK_FLOATS 2048             // 8 KB per chunk
#define CHUNK_BYTES (CHUNK_FLOATS * 4)
#define CHUNKS_PER_ROW (NC / CHUNK_FLOATS)            // 4
#define TOTAL_CHUNKS (ROWS_PER_CTA * CHUNKS_PER_ROW)  // 16

// Grid-level state (no cudaMalloc allowed). Self-resetting every run so CUDA
// graph replays are deterministic.
__device__ double       g_accum = 0.0;
__device__ unsigned int g_count = 0u;

// ---- minimal PTX helpers (mbarrier + bulk-async DMA) ----
__device__ __forceinline__ uint32_t smem_u32(const void* p) {
    return (uint32_t)__cvta_generic_to_shared(p);
}
__device__ __forceinline__ void mbar_init(uint32_t a, uint32_t cnt) {
    asm volatile("mbarrier.init.shared.b64 [%0], %1;" :: "r"(a), "r"(cnt) : "memory");
}
__device__ __forceinline__ void mbar_arrive(uint32_t a) {
    asm volatile("mbarrier.arrive.shared.b64 _, [%0];" :: "r"(a) : "memory");
}
__device__ __forceinline__ void mbar_expect_tx(uint32_t a, uint32_t bytes) {
    asm volatile("mbarrier.arrive.expect_tx.shared.b64 _, [%0], %1;"
                 :: "r"(a), "r"(bytes) : "memory");
}
__device__ __forceinline__ void mbar_wait(uint32_t a, uint32_t parity) {
    asm volatile(
        "{\n\t.reg .pred P;\n"
        "W_%=:\n\t"
        "mbarrier.try_wait.parity.acquire.cta.shared::cta.b64 P, [%0], %1, 0x989680;\n\t"
        "@P bra D_%=;\n\t"
        "bra W_%=;\n"
        "D_%=:\n\t}"
        :: "r"(a), "r"(parity) : "memory");
}
__device__ __forceinline__ void bulk_copy_g2s(uint32_t dst, const void* src,
                                              uint32_t bytes, uint32_t mbar) {
    asm volatile(
        "cp.async.bulk.shared::cluster.global.mbarrier::complete_tx::bytes "
        "[%0], [%1], %2, [%3];"
        :: "r"(dst), "l"(src), "r"(bytes), "r"(mbar) : "memory");
}

// Numerics: fp32 standard-normal inputs, sum(exp(x)) in [~50,1e6] -> no
// max-subtraction needed at 1e-3 tolerance.
//
// Evidence R5..R15: the LDG path plateaus at ~5.1 TB/s for this stream across
// every issue structure. This kernel switches paths entirely: bulk-async DMA
// (UBLKCP) GMEM->SMEM in 8 KB contiguous chunks through a 4-stage mbarrier
// ring; compute consumes from SMEM, fully decoupled from the DMA engine.
__global__ __launch_bounds__(THREADS) void mls_dma_kernel(
    const float* __restrict__ pred,
    const int*   __restrict__ labels,
    float*       __restrict__ out)
{
    extern __shared__ float buf[];               // STAGES * 2048 floats (32 KB)
    __shared__ __align__(8) unsigned long long full_bar[STAGES];
    __shared__ __align__(8) unsigned long long empty_bar[STAGES];
    __shared__ float spos[ROWS_PER_CTA * NK];    // positive logits, 4 rows x 8
    __shared__ float sred[ROWS_PER_CTA * 4];     // per-warp partials per row

    const int tid   = threadIdx.x;
    const int warp  = tid >> 5;
    const int lane  = tid & 31;
    const int row0  = blockIdx.x * ROWS_PER_CTA;

    uint32_t fb[STAGES], eb[STAGES];
#pragma unroll
    for (int s = 0; s < STAGES; s++) {
        fb[s] = smem_u32(&full_bar[s]);
        eb[s] = smem_u32(&empty_bar[s]);
    }

    if (tid == 0) {
#pragma unroll
        for (int s = 0; s < STAGES; s++) {
            mbar_init(fb[s], 1);         // producer's expect_tx arrival
            mbar_init(eb[s], THREADS);   // all consumers arrive
        }
    }

    // Positive logits: warp 0 gathers all 4 rows x 8 positives early.
    if (tid < ROWS_PER_CTA * NK) {
        const int r = tid >> 3, j = tid & 7;
        const int row = row0 + r;
        spos[tid] = __ldg(pred + (size_t)row * NC + __ldg(labels + row * NK + j));
    }
    __syncthreads();   // barriers initialized + visible before any use

    // ---- prologue: fill the ring ----
    if (tid == 0) {
#pragma unroll
        for (int k = 0; k < STAGES; k++) {
            const int r = k / CHUNKS_PER_ROW, c = k % CHUNKS_PER_ROW;
            mbar_expect_tx(fb[k], CHUNK_BYTES);
            bulk_copy_g2s(smem_u32(&buf[k * CHUNK_FLOATS]),
                          pred + (size_t)(row0 + r) * NC + c * CHUNK_FLOATS,
                          CHUNK_BYTES, fb[k]);
        }
    }

    double my_total = 0.0;          // thread 0 only
    float a0 = 0.f, a1 = 0.f, a2 = 0.f, a3 = 0.f;

    for (int k = 0; k < TOTAL_CHUNKS; k++) {
        const int      stage  = k & (STAGES - 1);
        const uint32_t parity = (k / STAGES) & 1;

        // ---- consume chunk k from SMEM ----
        mbar_wait(fb[stage], parity);
        const float4* sb = reinterpret_cast<const float4*>(&buf[stage * CHUNK_FLOATS]);
#pragma unroll
        for (int i = 0; i < 4; i++) {
            float4 v = sb[tid + i * THREADS];
            a0 += __expf(v.x); a1 += __expf(v.y);
            a2 += __expf(v.z); a3 += __expf(v.w);
        }
        mbar_arrive(eb[stage]);

        // ---- producer: refill this stage with chunk k+STAGES ----
        if (tid == 0 && k + STAGES < TOTAL_CHUNKS) {
            mbar_wait(eb[stage], parity);   // all 128 consumers done with stage
            const int kn = k + STAGES;
            const int r = kn / CHUNKS_PER_ROW, c = kn % CHUNKS_PER_ROW;
            mbar_expect_tx(fb[stage], CHUNK_BYTES);
            bulk_copy_g2s(smem_u32(&buf[stage * CHUNK_FLOATS]),
                          pred + (size_t)(row0 + r) * NC + c * CHUNK_FLOATS,
                          CHUNK_BYTES, fb[stage]);
        }

        // ---- row boundary: reduce and accumulate the row's loss terms ----
        if ((k & (CHUNKS_PER_ROW - 1)) == CHUNKS_PER_ROW - 1) {
            const int r = k / CHUNKS_PER_ROW;
            float s = (a0 + a1) + (a2 + a3);
            a0 = a1 = a2 = a3 = 0.f;
#pragma unroll
            for (int off = 16; off; off >>= 1)
                s += __shfl_xor_sync(0xFFFFFFFFu, s, off);
            if (lane == 0) sred[r * 4 + warp] = s;
            __syncthreads();
            if (tid == 0) {
                float S = sred[r * 4 + 0] + sred[r * 4 + 1]
                        + sred[r * 4 + 2] + sred[r * 4 + 3];
                float pe = 0.f;
#pragma unroll
                for (int j = 0; j < NK; j++) pe += __expf(spos[r * NK + j]);
                // logsumexp over the 8184 negatives
                const float lse_neg = __logf(S - pe);
                float acc = 0.f;
#pragma unroll
                for (int j = 0; j < NK; j++)
                    acc += log1pf(__expf(lse_neg - spos[r * NK + j]));
                my_total += (double)acc;
            }
        }
    }

    // ---- grid finalize: one atomic per CTA, last CTA writes + resets ----
    if (tid == 0) {
        atomicAdd(&g_accum, my_total);
        __threadfence();
        unsigned ticket = atomicAdd(&g_count, 1u);
        if (ticket == NBLK - 1) {
            unsigned long long bits =
                atomicExch(reinterpret_cast<unsigned long long*>(&g_accum), 0ULL);
            double total = __longlong_as_double(bits);
            out[0] = (float)(total / (double)((long long)NB * NK));
            g_count = 0u;
        }
    }
}

extern "C" void kernel_launch(void* const* d_in, const int* in_sizes, int n_in,
                              void* d_out, int out_size) {
    const float* pred   = (const float*)d_in[0];   // [B, C] float32
    const int*   labels = (const int*)d_in[1];     // [B, K] int32
    float* out = (float*)d_out;                    // scalar float32

    mls_dma_kernel<<<NBLK, THREADS, STAGES * CHUNK_BYTES>>>(pred, labels, out);
}